// round 9
// baseline (speedup 1.0000x reference)
#include <cuda_runtime.h>
#include <cuda_bf16.h>
#include <cstdint>

// Problem dims
#define MDIM 8192
#define NDIM 8192
#define DDIM 256
#define KSEL 256

// bf16x6 split-GEMM: A'=[h|m|h|l|h|m], B'=[h|h|m|h|l|m], K' = 6*256 = 1536
// product = h.h + m.h + h.m + l.h + h.l + m.m  (dropped terms <= 2^-27)
#define KBIG 1536
#define KCH 64
#define NCHUNK 24           // 1536 / 64
#define TM 128
#define TN 128
#define STAGES 3

// dynamic smem: per stage A(128x64 bf16=16KB) + B(16KB)
#define OFF_A(s) ((s) * 32768)
#define OFF_B(s) ((s) * 32768 + 16384)
#define SMEM_BYTES (STAGES * 32768)   // 96 KB

// ---------------- static device scratch ----------------
static __device__ __align__(256) float g_S[(size_t)MDIM * NDIM];          // 256 MB
static __device__ __align__(16) __nv_bfloat16 g_A2[(size_t)MDIM * KBIG];  // 24 MB
static __device__ __align__(16) __nv_bfloat16 g_B2[(size_t)NDIM * KBIG];  // 24 MB
static __device__ float g_Rpart[(size_t)MDIM * 64];
static __device__ float g_Cpart[(size_t)64 * NDIM];
static __device__ float g_invR[MDIM];
static __device__ float g_invC[NDIM];
static __device__ unsigned int g_hist[8192];
static __device__ unsigned int g_thresh;
static __device__ int g_candCount;
#define CAND_CAP (1 << 20)
static __device__ float g_candVal[CAND_CAP];
static __device__ int   g_candIdx[CAND_CAP];

// ---------------- PTX helpers (sm_80+ features only) ----------------
__device__ __forceinline__ uint32_t smem_u32(const void* p) {
    return (uint32_t)__cvta_generic_to_shared(p);
}
__device__ __forceinline__ void cp16(uint32_t s, const void* g) {
    asm volatile("cp.async.cg.shared.global [%0], [%1], 16;"
                 :: "r"(s), "l"(__cvta_generic_to_global(g)) : "memory");
}
__device__ __forceinline__ void cp_commit() {
    asm volatile("cp.async.commit_group;" ::: "memory");
}
template <int N> __device__ __forceinline__ void cp_wait() {
    asm volatile("cp.async.wait_group %0;" :: "n"(N) : "memory");
}
__device__ __forceinline__ void ldm_x4(uint32_t* r, uint32_t addr) {
    asm volatile("ldmatrix.sync.aligned.m8n8.x4.shared.b16 {%0,%1,%2,%3}, [%4];"
                 : "=r"(r[0]), "=r"(r[1]), "=r"(r[2]), "=r"(r[3]) : "r"(addr));
}
__device__ __forceinline__ void mma_bf16(float* d, const uint32_t* a, uint32_t b0, uint32_t b1) {
    asm volatile(
        "mma.sync.aligned.m16n8k16.row.col.f32.bf16.bf16.f32 "
        "{%0,%1,%2,%3}, {%4,%5,%6,%7}, {%8,%9}, {%0,%1,%2,%3};"
        : "+f"(d[0]), "+f"(d[1]), "+f"(d[2]), "+f"(d[3])
        : "r"(a[0]), "r"(a[1]), "r"(a[2]), "r"(a[3]), "r"(b0), "r"(b1));
}

// ---------------- init ----------------
__global__ void spm_init_kernel() {
    int t = blockIdx.x * blockDim.x + threadIdx.x;
    if (t < 8192) g_hist[t] = 0u;
    if (t == 8192) g_candCount = 0;
}

// ---------------- fp32 -> bf16 two-level split into 6 sections ----------------
// a = h + m + l + eps,  |m|<=2^-9|a|, |l|<=2^-18|a|, |eps|<=2^-27|a|
// A row sections (bf16 elem offsets): 0:h  256:m  512:h  768:l  1024:h  1280:m
// B row sections:                     0:h  256:h  512:m  768:h  1024:l  1280:m
__global__ void spm_split_kernel(const float* __restrict__ A, const float* __restrict__ B) {
    size_t idx = (size_t)blockIdx.x * blockDim.x + threadIdx.x;  // 0 .. 2*524288-1
    int mat = (int)(idx >> 19);
    int e = (int)(idx & ((1u << 19) - 1u));
    int row = e >> 6;
    int q = e & 63;
    const float4* src = (const float4*)(mat ? B : A);
    float4 a = src[e];

    float x[4] = {a.x, a.y, a.z, a.w};
    __nv_bfloat16 h[4], m[4], l[4];
#pragma unroll
    for (int i = 0; i < 4; i++) {
        h[i] = __float2bfloat16_rn(x[i]);
        float r1 = x[i] - __bfloat162float(h[i]);
        m[i] = __float2bfloat16_rn(r1);
        float r2 = r1 - __bfloat162float(m[i]);
        l[i] = __float2bfloat16_rn(r2);
    }
    __nv_bfloat162 hA = __halves2bfloat162(h[0], h[1]), hB = __halves2bfloat162(h[2], h[3]);
    __nv_bfloat162 mA = __halves2bfloat162(m[0], m[1]), mB = __halves2bfloat162(m[2], m[3]);
    __nv_bfloat162 lA = __halves2bfloat162(l[0], l[1]), lB = __halves2bfloat162(l[2], l[3]);

    __nv_bfloat16* dst = (mat ? g_B2 : g_A2) + (size_t)row * KBIG + q * 4;
    // section 0: h (both)
    *(__nv_bfloat162*)(dst + 0) = hA;      *(__nv_bfloat162*)(dst + 2) = hB;
    if (mat == 0) {  // A: [h, m, h, l, h, m]
        *(__nv_bfloat162*)(dst + 256)  = mA; *(__nv_bfloat162*)(dst + 258)  = mB;
        *(__nv_bfloat162*)(dst + 512)  = hA; *(__nv_bfloat162*)(dst + 514)  = hB;
        *(__nv_bfloat162*)(dst + 768)  = lA; *(__nv_bfloat162*)(dst + 770)  = lB;
        *(__nv_bfloat162*)(dst + 1024) = hA; *(__nv_bfloat162*)(dst + 1026) = hB;
        *(__nv_bfloat162*)(dst + 1280) = mA; *(__nv_bfloat162*)(dst + 1282) = mB;
    } else {         // B: [h, h, m, h, l, m]
        *(__nv_bfloat162*)(dst + 256)  = hA; *(__nv_bfloat162*)(dst + 258)  = hB;
        *(__nv_bfloat162*)(dst + 512)  = mA; *(__nv_bfloat162*)(dst + 514)  = mB;
        *(__nv_bfloat162*)(dst + 768)  = hA; *(__nv_bfloat162*)(dst + 770)  = hB;
        *(__nv_bfloat162*)(dst + 1024) = lA; *(__nv_bfloat162*)(dst + 1026) = lB;
        *(__nv_bfloat162*)(dst + 1280) = mA; *(__nv_bfloat162*)(dst + 1282) = mB;
    }
}

// ---------------- HMMA split-GEMM + exp epilogue + deterministic partial sums ----------------
__global__ __launch_bounds__(256, 2)
void spm_gemm_mma_kernel() {
    extern __shared__ char smem[];
    __shared__ float redR[128][5];
    __shared__ float redC[2][128];
    const uint32_t sb = smem_u32(smem);
    const int tid = threadIdx.x;
    const int lane = tid & 31, wid = tid >> 5;
    const int wr = wid >> 2, wc = wid & 3;          // warp grid 2 x 4
    const int bx = blockIdx.x, by = blockIdx.y;
    const int m0 = by * TM, n0 = bx * TN;

    // loader mapping: 256 threads cover 128 rows x 8 16B-segments (2 threads/row)
    const int lrow = tid >> 1;
    const int lseg = (tid & 1) * 4;
    const int sw = lrow & 7;
    const __nv_bfloat16* gA = g_A2 + (size_t)(m0 + lrow) * KBIG + lseg * 8;
    const __nv_bfloat16* gB = g_B2 + (size_t)(n0 + lrow) * KBIG + lseg * 8;
    const uint32_t sRowOff = lrow * 128;

#define LOAD_CHUNK(s, k) do {                                                   \
        uint32_t _a = sb + OFF_A(s) + sRowOff;                                  \
        uint32_t _b = sb + OFF_B(s) + sRowOff;                                  \
        _Pragma("unroll")                                                       \
        for (int j = 0; j < 4; j++) {                                           \
            cp16(_a + (((lseg + j) ^ sw) << 4), gA + (size_t)(k) * KCH + j * 8);\
            cp16(_b + (((lseg + j) ^ sw) << 4), gB + (size_t)(k) * KCH + j * 8);\
        }                                                                       \
        cp_commit();                                                            \
    } while (0)

    float acc[4][4][4];
#pragma unroll
    for (int mt = 0; mt < 4; mt++)
#pragma unroll
        for (int nt = 0; nt < 4; nt++)
#pragma unroll
            for (int i = 0; i < 4; i++) acc[mt][nt][i] = 0.0f;

    // ldmatrix addressing (x4: lane supplies row of matrix lane>>3)
    const int q = lane >> 3, rr = lane & 7;
    const int aRowBase = wr * 64 + rr + ((q & 1) << 3);   // + mt*16
    const int bRowBase = wc * 32 + rr + ((q & 1) << 3);   // + np*16
    const int kgHalf = q >> 1;                            // ks*2 + kgHalf

    LOAD_CHUNK(0, 0);
    LOAD_CHUNK(1, 1);

    for (int k = 0; k < NCHUNK; k++) {
        if (k + 2 < NCHUNK) LOAD_CHUNK((k + 2) % STAGES, k + 2);
        // Commit count after the load above = min(k+3, NCHUNK). Chunk k is
        // complete when pending groups <= min(k+3, NCHUNK) - (k+1).
        if (k <= NCHUNK - 3)      cp_wait<2>();
        else if (k == NCHUNK - 2) cp_wait<1>();
        else                      cp_wait<0>();
        __syncthreads();

        const int s = k % STAGES;
        const uint32_t aBase = sb + OFF_A(s);
        const uint32_t bBase = sb + OFF_B(s);
#pragma unroll
        for (int ks = 0; ks < 4; ks++) {
            const int kg = ks * 2 + kgHalf;
            uint32_t af[4][4], bf[2][4];
#pragma unroll
            for (int mt = 0; mt < 4; mt++) {
                int r = aRowBase + mt * 16;
                ldm_x4(af[mt], aBase + r * 128 + ((kg ^ (r & 7)) << 4));
            }
#pragma unroll
            for (int np = 0; np < 2; np++) {
                int r = bRowBase + np * 16;
                ldm_x4(bf[np], bBase + r * 128 + ((kg ^ (r & 7)) << 4));
            }
#pragma unroll
            for (int mt = 0; mt < 4; mt++)
#pragma unroll
                for (int nt = 0; nt < 4; nt++)
                    mma_bf16(acc[mt][nt], af[mt], bf[nt >> 1][nt & 1], bf[nt >> 1][(nt & 1) + 2]);
        }
        __syncthreads();
    }

    // ---------------- epilogue: exp, store S, deterministic row/col partials ----------------
    float rs[4][2];   // per m-tile, rows (lane>>2) and +8
    float cs[4][2];   // per n-tile, cols (lane&3)*2 + {0,1}
#pragma unroll
    for (int mt = 0; mt < 4; mt++) { rs[mt][0] = 0.0f; rs[mt][1] = 0.0f; }
#pragma unroll
    for (int nt = 0; nt < 4; nt++) { cs[nt][0] = 0.0f; cs[nt][1] = 0.0f; }

    const int rbase = m0 + wr * 64 + (lane >> 2);
    const int cbase = n0 + wc * 32 + (lane & 3) * 2;
#pragma unroll
    for (int mt = 0; mt < 4; mt++) {
#pragma unroll
        for (int p = 0; p < 2; p++) {
            const int grow = rbase + mt * 16 + p * 8;
            float* srow = g_S + (size_t)grow * NDIM + cbase;
#pragma unroll
            for (int nt = 0; nt < 4; nt++) {
                float e0 = __expf(fmaf(2.0f, acc[mt][nt][2 * p + 0], -2.0f));
                float e1 = __expf(fmaf(2.0f, acc[mt][nt][2 * p + 1], -2.0f));
                rs[mt][p] += e0 + e1;
                cs[nt][0] += e0;
                cs[nt][1] += e1;
                *(float2*)(srow + nt * 8) = make_float2(e0, e1);
            }
        }
    }

    // row partials: reduce over the 4 lanes sharing a row (xor 1, 2)
#pragma unroll
    for (int mt = 0; mt < 4; mt++) {
#pragma unroll
        for (int p = 0; p < 2; p++) {
            float v = rs[mt][p];
            v += __shfl_xor_sync(0xFFFFFFFFu, v, 1);
            v += __shfl_xor_sync(0xFFFFFFFFu, v, 2);
            if ((lane & 3) == 0) {
                int lr = wr * 64 + mt * 16 + (lane >> 2) + p * 8;
                redR[lr][wc] = v;
            }
        }
    }
    // col partials: reduce over the 8 lanes sharing cols (xor 4, 8, 16)
#pragma unroll
    for (int nt = 0; nt < 4; nt++) {
#pragma unroll
        for (int j = 0; j < 2; j++) {
            float v = cs[nt][j];
            v += __shfl_xor_sync(0xFFFFFFFFu, v, 4);
            v += __shfl_xor_sync(0xFFFFFFFFu, v, 8);
            v += __shfl_xor_sync(0xFFFFFFFFu, v, 16);
            if (lane < 4) {
                int lc = wc * 32 + nt * 8 + lane * 2 + j;
                redC[wr][lc] = v;
            }
        }
    }
    __syncthreads();
    if (tid < 128) {
        float s = ((redR[tid][0] + redR[tid][1]) + redR[tid][2]) + redR[tid][3];
        g_Rpart[(size_t)(m0 + tid) * 64 + bx] = s;
        g_Cpart[(size_t)by * NDIM + (n0 + tid)] = redC[0][tid] + redC[1][tid];
    }
#undef LOAD_CHUNK
}

// ---------------- deterministic reduction of row/col sums -> reciprocals ----------------
__global__ void spm_reduce_rc_kernel() {
    int t = blockIdx.x * blockDim.x + threadIdx.x;
    if (t < MDIM) {
        float s = 0.0f;
        const float* p = g_Rpart + (size_t)t * 64;
#pragma unroll 8
        for (int i = 0; i < 64; i++) s += p[i];
        g_invR[t] = 1.0f / s;
    } else if (t < MDIM + NDIM) {
        int n = t - MDIM;
        float s = 0.0f;
        for (int i = 0; i < 64; i++) s += g_Cpart[(size_t)i * NDIM + n];
        g_invC[n] = 1.0f / s;
    }
}

// ---------------- histogram of v = S^2 * invR * invC over float-bit buckets ----------------
__global__ void spm_hist_kernel() {
    __shared__ unsigned int h[8192];
    for (int i = threadIdx.x; i < 8192; i += 256) h[i] = 0u;
    __syncthreads();

    const float4* S4 = (const float4*)g_S;
    const size_t base4 = (size_t)blockIdx.x * 4096;
#pragma unroll 4
    for (int j = 0; j < 16; j++) {
        size_t idx4 = base4 + (size_t)j * 256 + threadIdx.x;
        float4 s = S4[idx4];
        size_t i0 = idx4 * 4;
        int m = (int)(i0 >> 13);
        int n = (int)(i0 & 8191);
        float fr = g_invR[m];
        float4 ic = *(const float4*)(g_invC + n);
        float v0 = s.x * s.x * fr * ic.x;
        float v1 = s.y * s.y * fr * ic.y;
        float v2 = s.z * s.z * fr * ic.z;
        float v3 = s.w * s.w * fr * ic.w;
        atomicAdd(&h[min(__float_as_uint(v0) >> 18, 8191u)], 1u);
        atomicAdd(&h[min(__float_as_uint(v1) >> 18, 8191u)], 1u);
        atomicAdd(&h[min(__float_as_uint(v2) >> 18, 8191u)], 1u);
        atomicAdd(&h[min(__float_as_uint(v3) >> 18, 8191u)], 1u);
    }
    __syncthreads();
    for (int i = threadIdx.x; i < 8192; i += 256) {
        unsigned int c = h[i];
        if (c) atomicAdd(&g_hist[i], c);
    }
}

// ---------------- find threshold bucket such that cum count >= 256 ----------------
__global__ void spm_thresh_kernel() {
    if (threadIdx.x == 0) {
        unsigned int cum = 0;
        int b = 8191;
        for (; b >= 0; b--) {
            cum += g_hist[b];
            if (cum >= KSEL) break;
        }
        if (b < 0) b = 0;
        g_thresh = ((unsigned int)b) << 18;
    }
}

// ---------------- gather candidates >= threshold ----------------
__global__ void spm_select_kernel() {
    const unsigned int thr = g_thresh;
    const float4* S4 = (const float4*)g_S;
    const size_t base4 = (size_t)blockIdx.x * 4096;
#pragma unroll 4
    for (int j = 0; j < 16; j++) {
        size_t idx4 = base4 + (size_t)j * 256 + threadIdx.x;
        float4 s = S4[idx4];
        size_t i0 = idx4 * 4;
        int m = (int)(i0 >> 13);
        int n = (int)(i0 & 8191);
        float fr = g_invR[m];
        float4 ic = *(const float4*)(g_invC + n);
        float v[4];
        v[0] = s.x * s.x * fr * ic.x;
        v[1] = s.y * s.y * fr * ic.y;
        v[2] = s.z * s.z * fr * ic.z;
        v[3] = s.w * s.w * fr * ic.w;
#pragma unroll
        for (int u = 0; u < 4; u++) {
            if (__float_as_uint(v[u]) >= thr) {
                int p = atomicAdd(&g_candCount, 1);
                if (p < CAND_CAP) {
                    g_candVal[p] = v[u];
                    g_candIdx[p] = (int)(i0 + u);
                }
            }
        }
    }
}

// ---------------- exact rank-based top-256 (matches lax.top_k tie-break) ----------------
__global__ void spm_topk_kernel(float* __restrict__ out) {
    int K = g_candCount;
    if (K > CAND_CAP) K = CAND_CAP;
    for (int c = threadIdx.x; c < K; c += blockDim.x) {
        const float vc = g_candVal[c];
        const int ic = g_candIdx[c];
        int rank = 0;
        for (int j = 0; j < K; j++) {
            const float vj = g_candVal[j];
            const int ij = g_candIdx[j];
            rank += (vj > vc) || (vj == vc && ij < ic);
        }
        if (rank < KSEL) {
            out[rank]            = (float)(ic >> 13);   // ref index = i // 8192
            out[KSEL + rank]     = (float)(ic & 8191);  // src index = i % 8192
            out[2 * KSEL + rank] = vc;                  // score
        }
    }
}

// ---------------- launch ----------------
extern "C" void kernel_launch(void* const* d_in, const int* in_sizes, int n_in,
                              void* d_out, int out_size) {
    const float* ref = (const float*)d_in[0];  // [8192, 256]
    const float* src = (const float*)d_in[1];  // [8192, 256]
    float* out = (float*)d_out;                // [768]: ref_idx | src_idx | scores

    cudaFuncSetAttribute(spm_gemm_mma_kernel,
                         cudaFuncAttributeMaxDynamicSharedMemorySize, SMEM_BYTES);

    spm_init_kernel<<<33, 256>>>();
    spm_split_kernel<<<4096, 256>>>(ref, src);
    spm_gemm_mma_kernel<<<dim3(64, 64), 256, SMEM_BYTES>>>();
    spm_reduce_rc_kernel<<<64, 256>>>();
    spm_hist_kernel<<<4096, 256>>>();
    spm_thresh_kernel<<<1, 32>>>();
    spm_select_kernel<<<4096, 256>>>();
    spm_topk_kernel<<<1, 256>>>(out);
}

// round 12
// speedup vs baseline: 1.1658x; 1.1658x over previous
#include <cuda_runtime.h>
#include <cuda_bf16.h>
#include <cstdint>

// Problem dims
#define MDIM 8192
#define NDIM 8192
#define DDIM 256
#define KSEL 256

// bf16x6 split-GEMM: A'=[h|m|h|l|h|m], B'=[h|h|m|h|l|m], K' = 6*256 = 1536
#define KBIG 1536
#define KCH 64
#define NCHUNK 24           // 1536 / 64
#define TM 128
#define TN 128
#define STAGES 3

#define OFF_A(s) ((s) * 32768)
#define OFF_B(s) ((s) * 32768 + 16384)
#define SMEM_BYTES (STAGES * 32768)   // 96 KB

#define NTILES 4096         // 64 x 64 tiles of 128x128

// ---------------- static device scratch ----------------
static __device__ __align__(256) float g_S[(size_t)MDIM * NDIM];          // 256 MB
static __device__ __align__(16) __nv_bfloat16 g_A2[(size_t)MDIM * KBIG];  // 24 MB
static __device__ __align__(16) __nv_bfloat16 g_B2[(size_t)NDIM * KBIG];  // 24 MB
static __device__ float g_Rpart[(size_t)MDIM * 64];
static __device__ float g_Cpart[(size_t)64 * NDIM];
static __device__ float g_invR[MDIM];
static __device__ float g_invC[NDIM];
static __device__ float g_tileMaxS[NTILES];
static __device__ float g_tileU[NTILES];
static __device__ unsigned int g_thresh;   // float bits of threshold
static __device__ int g_candCount;
#define CAND_CAP (1 << 20)
static __device__ float g_candVal[CAND_CAP];
static __device__ int   g_candIdx[CAND_CAP];

// ---------------- PTX helpers (sm_80+ features only) ----------------
__device__ __forceinline__ uint32_t smem_u32(const void* p) {
    return (uint32_t)__cvta_generic_to_shared(p);
}
__device__ __forceinline__ void cp16(uint32_t s, const void* g) {
    asm volatile("cp.async.cg.shared.global [%0], [%1], 16;"
                 :: "r"(s), "l"(__cvta_generic_to_global(g)) : "memory");
}
__device__ __forceinline__ void cp_commit() {
    asm volatile("cp.async.commit_group;" ::: "memory");
}
template <int N> __device__ __forceinline__ void cp_wait() {
    asm volatile("cp.async.wait_group %0;" :: "n"(N) : "memory");
}
__device__ __forceinline__ void ldm_x4(uint32_t* r, uint32_t addr) {
    asm volatile("ldmatrix.sync.aligned.m8n8.x4.shared.b16 {%0,%1,%2,%3}, [%4];"
                 : "=r"(r[0]), "=r"(r[1]), "=r"(r[2]), "=r"(r[3]) : "r"(addr));
}
__device__ __forceinline__ void mma_bf16(float* d, const uint32_t* a, uint32_t b0, uint32_t b1) {
    asm volatile(
        "mma.sync.aligned.m16n8k16.row.col.f32.bf16.bf16.f32 "
        "{%0,%1,%2,%3}, {%4,%5,%6,%7}, {%8,%9}, {%0,%1,%2,%3};"
        : "+f"(d[0]), "+f"(d[1]), "+f"(d[2]), "+f"(d[3])
        : "r"(a[0]), "r"(a[1]), "r"(a[2]), "r"(a[3]), "r"(b0), "r"(b1));
}

// ---------------- init ----------------
__global__ void spm_init_kernel() {
    if (blockIdx.x == 0 && threadIdx.x == 0) g_candCount = 0;
}

// ---------------- fp32 -> bf16 two-level split into 6 sections ----------------
__global__ void spm_split_kernel(const float* __restrict__ A, const float* __restrict__ B) {
    size_t idx = (size_t)blockIdx.x * blockDim.x + threadIdx.x;
    int mat = (int)(idx >> 19);
    int e = (int)(idx & ((1u << 19) - 1u));
    int row = e >> 6;
    int q = e & 63;
    const float4* src = (const float4*)(mat ? B : A);
    float4 a = src[e];

    float x[4] = {a.x, a.y, a.z, a.w};
    __nv_bfloat16 h[4], m[4], l[4];
#pragma unroll
    for (int i = 0; i < 4; i++) {
        h[i] = __float2bfloat16_rn(x[i]);
        float r1 = x[i] - __bfloat162float(h[i]);
        m[i] = __float2bfloat16_rn(r1);
        float r2 = r1 - __bfloat162float(m[i]);
        l[i] = __float2bfloat16_rn(r2);
    }
    __nv_bfloat162 hA = __halves2bfloat162(h[0], h[1]), hB = __halves2bfloat162(h[2], h[3]);
    __nv_bfloat162 mA = __halves2bfloat162(m[0], m[1]), mB = __halves2bfloat162(m[2], m[3]);
    __nv_bfloat162 lA = __halves2bfloat162(l[0], l[1]), lB = __halves2bfloat162(l[2], l[3]);

    __nv_bfloat16* dst = (mat ? g_B2 : g_A2) + (size_t)row * KBIG + q * 4;
    *(__nv_bfloat162*)(dst + 0) = hA;      *(__nv_bfloat162*)(dst + 2) = hB;
    if (mat == 0) {  // A: [h, m, h, l, h, m]
        *(__nv_bfloat162*)(dst + 256)  = mA; *(__nv_bfloat162*)(dst + 258)  = mB;
        *(__nv_bfloat162*)(dst + 512)  = hA; *(__nv_bfloat162*)(dst + 514)  = hB;
        *(__nv_bfloat162*)(dst + 768)  = lA; *(__nv_bfloat162*)(dst + 770)  = lB;
        *(__nv_bfloat162*)(dst + 1024) = hA; *(__nv_bfloat162*)(dst + 1026) = hB;
        *(__nv_bfloat162*)(dst + 1280) = mA; *(__nv_bfloat162*)(dst + 1282) = mB;
    } else {         // B: [h, h, m, h, l, m]
        *(__nv_bfloat162*)(dst + 256)  = hA; *(__nv_bfloat162*)(dst + 258)  = hB;
        *(__nv_bfloat162*)(dst + 512)  = mA; *(__nv_bfloat162*)(dst + 514)  = mB;
        *(__nv_bfloat162*)(dst + 768)  = hA; *(__nv_bfloat162*)(dst + 770)  = hB;
        *(__nv_bfloat162*)(dst + 1024) = lA; *(__nv_bfloat162*)(dst + 1026) = lB;
        *(__nv_bfloat162*)(dst + 1280) = mA; *(__nv_bfloat162*)(dst + 1282) = mB;
    }
}

// ---------------- HMMA split-GEMM + exp epilogue + partial sums + tile max ----------------
__global__ __launch_bounds__(256, 2)
void spm_gemm_mma_kernel() {
    extern __shared__ char smem[];
    __shared__ float redR[128][5];
    __shared__ float redC[2][128];
    __shared__ float smax[8];
    const uint32_t sb = smem_u32(smem);
    const int tid = threadIdx.x;
    const int lane = tid & 31, wid = tid >> 5;
    const int wr = wid >> 2, wc = wid & 3;          // warp grid 2 x 4
    const int bx = blockIdx.x, by = blockIdx.y;
    const int m0 = by * TM, n0 = bx * TN;

    const int lrow = tid >> 1;
    const int lseg = (tid & 1) * 4;
    const int sw = lrow & 7;
    const __nv_bfloat16* gA = g_A2 + (size_t)(m0 + lrow) * KBIG + lseg * 8;
    const __nv_bfloat16* gB = g_B2 + (size_t)(n0 + lrow) * KBIG + lseg * 8;
    const uint32_t sRowOff = lrow * 128;

#define LOAD_CHUNK(s, k) do {                                                   \
        uint32_t _a = sb + OFF_A(s) + sRowOff;                                  \
        uint32_t _b = sb + OFF_B(s) + sRowOff;                                  \
        _Pragma("unroll")                                                       \
        for (int j = 0; j < 4; j++) {                                           \
            cp16(_a + (((lseg + j) ^ sw) << 4), gA + (size_t)(k) * KCH + j * 8);\
            cp16(_b + (((lseg + j) ^ sw) << 4), gB + (size_t)(k) * KCH + j * 8);\
        }                                                                       \
        cp_commit();                                                            \
    } while (0)

    float acc[4][4][4];
#pragma unroll
    for (int mt = 0; mt < 4; mt++)
#pragma unroll
        for (int nt = 0; nt < 4; nt++)
#pragma unroll
            for (int i = 0; i < 4; i++) acc[mt][nt][i] = 0.0f;

    const int q = lane >> 3, rr = lane & 7;
    const int aRowBase = wr * 64 + rr + ((q & 1) << 3);
    const int bRowBase = wc * 32 + rr + ((q & 1) << 3);
    const int kgHalf = q >> 1;

    LOAD_CHUNK(0, 0);
    LOAD_CHUNK(1, 1);

#pragma unroll 3
    for (int k = 0; k < NCHUNK; k++) {
        if (k + 2 < NCHUNK) LOAD_CHUNK((k + 2) % STAGES, k + 2);
        if (k <= NCHUNK - 3)      cp_wait<2>();
        else if (k == NCHUNK - 2) cp_wait<1>();
        else                      cp_wait<0>();
        __syncthreads();

        const int s = k % STAGES;
        const uint32_t aBase = sb + OFF_A(s);
        const uint32_t bBase = sb + OFF_B(s);
#pragma unroll
        for (int ks = 0; ks < 4; ks++) {
            const int kg = ks * 2 + kgHalf;
            uint32_t af[4][4], bf[2][4];
#pragma unroll
            for (int mt = 0; mt < 4; mt++) {
                int r = aRowBase + mt * 16;
                ldm_x4(af[mt], aBase + r * 128 + ((kg ^ (r & 7)) << 4));
            }
#pragma unroll
            for (int np = 0; np < 2; np++) {
                int r = bRowBase + np * 16;
                ldm_x4(bf[np], bBase + r * 128 + ((kg ^ (r & 7)) << 4));
            }
#pragma unroll
            for (int mt = 0; mt < 4; mt++)
#pragma unroll
                for (int nt = 0; nt < 4; nt++)
                    mma_bf16(acc[mt][nt], af[mt], bf[nt >> 1][nt & 1], bf[nt >> 1][(nt & 1) + 2]);
        }
        __syncthreads();
    }

    // ---------------- epilogue ----------------
    float rs[4][2];
    float cs[4][2];
#pragma unroll
    for (int mt = 0; mt < 4; mt++) { rs[mt][0] = 0.0f; rs[mt][1] = 0.0f; }
#pragma unroll
    for (int nt = 0; nt < 4; nt++) { cs[nt][0] = 0.0f; cs[nt][1] = 0.0f; }
    float tmax = 0.0f;

    const int rbase = m0 + wr * 64 + (lane >> 2);
    const int cbase = n0 + wc * 32 + (lane & 3) * 2;
#pragma unroll
    for (int mt = 0; mt < 4; mt++) {
#pragma unroll
        for (int p = 0; p < 2; p++) {
            const int grow = rbase + mt * 16 + p * 8;
            float* srow = g_S + (size_t)grow * NDIM + cbase;
#pragma unroll
            for (int nt = 0; nt < 4; nt++) {
                float e0 = __expf(fmaf(2.0f, acc[mt][nt][2 * p + 0], -2.0f));
                float e1 = __expf(fmaf(2.0f, acc[mt][nt][2 * p + 1], -2.0f));
                rs[mt][p] += e0 + e1;
                cs[nt][0] += e0;
                cs[nt][1] += e1;
                tmax = fmaxf(tmax, fmaxf(e0, e1));
                *(float2*)(srow + nt * 8) = make_float2(e0, e1);
            }
        }
    }

#pragma unroll
    for (int mt = 0; mt < 4; mt++) {
#pragma unroll
        for (int p = 0; p < 2; p++) {
            float v = rs[mt][p];
            v += __shfl_xor_sync(0xFFFFFFFFu, v, 1);
            v += __shfl_xor_sync(0xFFFFFFFFu, v, 2);
            if ((lane & 3) == 0) {
                int lr = wr * 64 + mt * 16 + (lane >> 2) + p * 8;
                redR[lr][wc] = v;
            }
        }
    }
#pragma unroll
    for (int nt = 0; nt < 4; nt++) {
#pragma unroll
        for (int j = 0; j < 2; j++) {
            float v = cs[nt][j];
            v += __shfl_xor_sync(0xFFFFFFFFu, v, 4);
            v += __shfl_xor_sync(0xFFFFFFFFu, v, 8);
            v += __shfl_xor_sync(0xFFFFFFFFu, v, 16);
            if (lane < 4) {
                int lc = wc * 32 + nt * 8 + lane * 2 + j;
                redC[wr][lc] = v;
            }
        }
    }
    // tile max S
#pragma unroll
    for (int d = 16; d >= 1; d >>= 1)
        tmax = fmaxf(tmax, __shfl_xor_sync(0xFFFFFFFFu, tmax, d));
    if (lane == 0) smax[wid] = tmax;
    __syncthreads();
    if (tid == 0) {
        float s = smax[0];
#pragma unroll
        for (int i = 1; i < 8; i++) s = fmaxf(s, smax[i]);
        g_tileMaxS[by * 64 + bx] = s;
    }
    if (tid < 128) {
        float s = ((redR[tid][0] + redR[tid][1]) + redR[tid][2]) + redR[tid][3];
        g_Rpart[(size_t)(m0 + tid) * 64 + bx] = s;
        g_Cpart[(size_t)by * NDIM + (n0 + tid)] = redC[0][tid] + redC[1][tid];
    }
#undef LOAD_CHUNK
}

// ---------------- deterministic reduction of row/col sums -> reciprocals ----------------
__global__ void spm_reduce_rc_kernel() {
    int t = blockIdx.x * blockDim.x + threadIdx.x;
    if (t < MDIM) {
        float s = 0.0f;
        const float* p = g_Rpart + (size_t)t * 64;
#pragma unroll 8
        for (int i = 0; i < 64; i++) s += p[i];
        g_invR[t] = 1.0f / s;
    } else if (t < MDIM + NDIM) {
        int n = t - MDIM;
        float s = 0.0f;
        for (int i = 0; i < 64; i++) s += g_Cpart[(size_t)i * NDIM + n];
        g_invC[n] = 1.0f / s;
    }
}

// ---------------- tile bounds + threshold (single block, 1024 threads) ----------------
// Per tile t: L_t = (maxS^2)*rgMin*cgMin <= exact v of the tile-max element.
//            U_t = (maxS^2)*rgMax*cgMax*(1+1e-5) >= every v in the tile.
// thr = float bucket floor of 256th-largest L_t  =>  thr <= v_k (global 256th v).
__global__ void spm_thr_kernel() {
    __shared__ float rgMin[64], rgMax[64], cgMin[64], cgMax[64];
    __shared__ unsigned int hist[8192];
    __shared__ unsigned int gsum[256];
    const int tid = threadIdx.x;

    for (int i = tid; i < 8192; i += 1024) hist[i] = 0u;
    if (tid < 64) {
        float mn = 3.4e38f, mx = 0.0f;
        const float* p = g_invR + tid * 128;
        for (int i = 0; i < 128; i++) { float v = p[i]; mn = fminf(mn, v); mx = fmaxf(mx, v); }
        rgMin[tid] = mn; rgMax[tid] = mx;
    } else if (tid < 128) {
        int g = tid - 64;
        float mn = 3.4e38f, mx = 0.0f;
        const float* p = g_invC + g * 128;
        for (int i = 0; i < 128; i++) { float v = p[i]; mn = fminf(mn, v); mx = fmaxf(mx, v); }
        cgMin[g] = mn; cgMax[g] = mx;
    }
    __syncthreads();

    for (int t = tid; t < NTILES; t += 1024) {
        int ty = t >> 6, tx = t & 63;
        float s = g_tileMaxS[t];
        float s2 = s * s;
        float L = s2 * rgMin[ty] * cgMin[tx];
        float U = s2 * rgMax[ty] * cgMax[tx] * 1.00001f;
        g_tileU[t] = U;
        atomicAdd(&hist[min(__float_as_uint(L) >> 18, 8191u)], 1u);
    }
    __syncthreads();

    // group sums (32 buckets per group), then serial scan over 256 groups
    if (tid < 256) {
        unsigned int s = 0;
        for (int i = 0; i < 32; i++) s += hist[tid * 32 + i];
        gsum[tid] = s;
    }
    __syncthreads();
    if (tid == 0) {
        unsigned int cum = 0;
        int g = 255;
        for (; g >= 0; g--) {
            if (cum + gsum[g] >= KSEL) break;
            cum += gsum[g];
        }
        if (g < 0) g = 0;
        int b = g * 32 + 31;
        for (; b > g * 32; b--) {
            cum += hist[b];
            if (cum >= KSEL) break;
        }
        if (cum < KSEL && b == g * 32) { /* fall through: use lowest bucket of group */ }
        g_thresh = ((unsigned int)b) << 18;
    }
}

// ---------------- gather candidates from tiles whose upper bound passes ----------------
__global__ void spm_select_kernel() {
    const int t = blockIdx.x;
    const float thrF = __uint_as_float(g_thresh);
    if (g_tileU[t] < thrF) return;
    const int ty = t >> 6, tx = t & 63;
    const int tid = threadIdx.x;

#pragma unroll 4
    for (int it = 0; it < 16; it++) {
        int f = it * 256 + tid;          // 0..4095 float4s in tile
        int r = f >> 5;                  // 0..127
        int c4 = f & 31;                 // 0..31
        int R = ty * 128 + r;
        int C = tx * 128 + c4 * 4;
        float4 s = *(const float4*)(g_S + (size_t)R * NDIM + C);
        float fr = g_invR[R];
        float4 ic = *(const float4*)(g_invC + C);
        float v[4];
        v[0] = s.x * s.x * fr * ic.x;
        v[1] = s.y * s.y * fr * ic.y;
        v[2] = s.z * s.z * fr * ic.z;
        v[3] = s.w * s.w * fr * ic.w;
        size_t i0 = (size_t)R * NDIM + C;
#pragma unroll
        for (int u = 0; u < 4; u++) {
            if (v[u] >= thrF) {
                int p = atomicAdd(&g_candCount, 1);
                if (p < CAND_CAP) {
                    g_candVal[p] = v[u];
                    g_candIdx[p] = (int)(i0 + u);
                }
            }
        }
    }
}

// ---------------- exact rank-based top-256 (matches lax.top_k tie-break) ----------------
__global__ void spm_topk_kernel(float* __restrict__ out) {
    int K = g_candCount;
    if (K > CAND_CAP) K = CAND_CAP;
    for (int c = blockIdx.x * blockDim.x + threadIdx.x; c < K;
         c += gridDim.x * blockDim.x) {
        const float vc = g_candVal[c];
        const int ic = g_candIdx[c];
        int rank = 0;
        for (int j = 0; j < K; j++) {
            const float vj = g_candVal[j];
            const int ij = g_candIdx[j];
            rank += (vj > vc) || (vj == vc && ij < ic);
        }
        if (rank < KSEL) {
            out[rank]            = (float)(ic >> 13);   // ref index = i // 8192
            out[KSEL + rank]     = (float)(ic & 8191);  // src index = i % 8192
            out[2 * KSEL + rank] = vc;                  // score
        }
    }
}

// ---------------- launch ----------------
extern "C" void kernel_launch(void* const* d_in, const int* in_sizes, int n_in,
                              void* d_out, int out_size) {
    const float* ref = (const float*)d_in[0];  // [8192, 256]
    const float* src = (const float*)d_in[1];  // [8192, 256]
    float* out = (float*)d_out;                // [768]: ref_idx | src_idx | scores

    cudaFuncSetAttribute(spm_gemm_mma_kernel,
                         cudaFuncAttributeMaxDynamicSharedMemorySize, SMEM_BYTES);

    spm_init_kernel<<<1, 32>>>();
    spm_split_kernel<<<4096, 256>>>(ref, src);
    spm_gemm_mma_kernel<<<dim3(64, 64), 256, SMEM_BYTES>>>();
    spm_reduce_rc_kernel<<<64, 256>>>();
    spm_thr_kernel<<<1, 1024>>>();
    spm_select_kernel<<<NTILES, 256>>>();
    spm_topk_kernel<<<64, 256>>>(out);
}

// round 17
// speedup vs baseline: 1.1660x; 1.0002x over previous
#include <cuda_runtime.h>
#include <cuda_bf16.h>
#include <cstdint>

// Problem dims
#define MDIM 8192
#define NDIM 8192
#define DDIM 256
#define KSEL 256

// bf16x6 split-GEMM: A'=[h|m|h|l|h|m], B'=[h|h|m|h|l|m], K' = 6*256 = 1536
#define KBIG 1536
#define KCH 64
#define NCHUNK 24           // 1536 / 64
#define TM 128
#define TN 128
#define STAGES 3

#define OFF_A(s) ((s) * 32768)
#define OFF_B(s) ((s) * 32768 + 16384)
#define SMEM_BYTES (STAGES * 32768)   // 96 KB

#define NTILES 4096         // 64 x 64 tiles of 128x128

// ---------------- static device scratch ----------------
static __device__ __align__(256) float g_S[(size_t)MDIM * NDIM];          // 256 MB
static __device__ __align__(16) __nv_bfloat16 g_A2[(size_t)MDIM * KBIG];  // 24 MB
static __device__ __align__(16) __nv_bfloat16 g_B2[(size_t)NDIM * KBIG];  // 24 MB
static __device__ float g_Rpart[(size_t)MDIM * 64];
static __device__ float g_Cpart[(size_t)64 * NDIM];
static __device__ float g_invR[MDIM];
static __device__ float g_invC[NDIM];
static __device__ float g_tileMaxS[NTILES];
static __device__ float g_tileU[NTILES];
static __device__ unsigned int g_thresh;   // float bits of threshold
static __device__ int g_candCount;
#define CAND_CAP (1 << 20)
static __device__ float g_candVal[CAND_CAP];
static __device__ int   g_candIdx[CAND_CAP];

// ---------------- PTX helpers (sm_80+ features only) ----------------
__device__ __forceinline__ uint32_t smem_u32(const void* p) {
    return (uint32_t)__cvta_generic_to_shared(p);
}
__device__ __forceinline__ void cp16(uint32_t s, const void* g) {
    asm volatile("cp.async.cg.shared.global [%0], [%1], 16;"
                 :: "r"(s), "l"(__cvta_generic_to_global(g)) : "memory");
}
__device__ __forceinline__ void cp_commit() {
    asm volatile("cp.async.commit_group;" ::: "memory");
}
template <int N> __device__ __forceinline__ void cp_wait() {
    asm volatile("cp.async.wait_group %0;" :: "n"(N) : "memory");
}
__device__ __forceinline__ void ldm_x4(uint32_t* r, uint32_t addr) {
    asm volatile("ldmatrix.sync.aligned.m8n8.x4.shared.b16 {%0,%1,%2,%3}, [%4];"
                 : "=r"(r[0]), "=r"(r[1]), "=r"(r[2]), "=r"(r[3]) : "r"(addr));
}
__device__ __forceinline__ void mma_bf16(float* d, const uint32_t* a, uint32_t b0, uint32_t b1) {
    asm volatile(
        "mma.sync.aligned.m16n8k16.row.col.f32.bf16.bf16.f32 "
        "{%0,%1,%2,%3}, {%4,%5,%6,%7}, {%8,%9}, {%0,%1,%2,%3};"
        : "+f"(d[0]), "+f"(d[1]), "+f"(d[2]), "+f"(d[3])
        : "r"(a[0]), "r"(a[1]), "r"(a[2]), "r"(a[3]), "r"(b0), "r"(b1));
}

// ---------------- init ----------------
__global__ void spm_init_kernel() {
    if (blockIdx.x == 0 && threadIdx.x == 0) g_candCount = 0;
}

// ---------------- no-op pad so the GEMM is launch #4 (ncu captures #4) ----------------
__global__ void spm_nop_kernel() {}

// ---------------- fp32 -> bf16 two-level split into 6 sections ----------------
__global__ void spm_split_kernel(const float* __restrict__ A, const float* __restrict__ B) {
    size_t idx = (size_t)blockIdx.x * blockDim.x + threadIdx.x;
    int mat = (int)(idx >> 19);
    int e = (int)(idx & ((1u << 19) - 1u));
    int row = e >> 6;
    int q = e & 63;
    const float4* src = (const float4*)(mat ? B : A);
    float4 a = src[e];

    float x[4] = {a.x, a.y, a.z, a.w};
    __nv_bfloat16 h[4], m[4], l[4];
#pragma unroll
    for (int i = 0; i < 4; i++) {
        h[i] = __float2bfloat16_rn(x[i]);
        float r1 = x[i] - __bfloat162float(h[i]);
        m[i] = __float2bfloat16_rn(r1);
        float r2 = r1 - __bfloat162float(m[i]);
        l[i] = __float2bfloat16_rn(r2);
    }
    __nv_bfloat162 hA = __halves2bfloat162(h[0], h[1]), hB = __halves2bfloat162(h[2], h[3]);
    __nv_bfloat162 mA = __halves2bfloat162(m[0], m[1]), mB = __halves2bfloat162(m[2], m[3]);
    __nv_bfloat162 lA = __halves2bfloat162(l[0], l[1]), lB = __halves2bfloat162(l[2], l[3]);

    __nv_bfloat16* dst = (mat ? g_B2 : g_A2) + (size_t)row * KBIG + q * 4;
    *(__nv_bfloat162*)(dst + 0) = hA;      *(__nv_bfloat162*)(dst + 2) = hB;
    if (mat == 0) {  // A: [h, m, h, l, h, m]
        *(__nv_bfloat162*)(dst + 256)  = mA; *(__nv_bfloat162*)(dst + 258)  = mB;
        *(__nv_bfloat162*)(dst + 512)  = hA; *(__nv_bfloat162*)(dst + 514)  = hB;
        *(__nv_bfloat162*)(dst + 768)  = lA; *(__nv_bfloat162*)(dst + 770)  = lB;
        *(__nv_bfloat162*)(dst + 1024) = hA; *(__nv_bfloat162*)(dst + 1026) = hB;
        *(__nv_bfloat162*)(dst + 1280) = mA; *(__nv_bfloat162*)(dst + 1282) = mB;
    } else {         // B: [h, h, m, h, l, m]
        *(__nv_bfloat162*)(dst + 256)  = hA; *(__nv_bfloat162*)(dst + 258)  = hB;
        *(__nv_bfloat162*)(dst + 512)  = mA; *(__nv_bfloat162*)(dst + 514)  = mB;
        *(__nv_bfloat162*)(dst + 768)  = hA; *(__nv_bfloat162*)(dst + 770)  = hB;
        *(__nv_bfloat162*)(dst + 1024) = lA; *(__nv_bfloat162*)(dst + 1026) = lB;
        *(__nv_bfloat162*)(dst + 1280) = mA; *(__nv_bfloat162*)(dst + 1282) = mB;
    }
}

// ---------------- HMMA split-GEMM + exp epilogue + partial sums + tile max ----------------
__global__ __launch_bounds__(256, 2)
void spm_gemm_mma_kernel() {
    extern __shared__ char smem[];
    __shared__ float redR[128][5];
    __shared__ float redC[2][128];
    __shared__ float smax[8];
    const uint32_t sb = smem_u32(smem);
    const int tid = threadIdx.x;
    const int lane = tid & 31, wid = tid >> 5;
    const int wr = wid >> 2, wc = wid & 3;          // warp grid 2 x 4
    const int bx = blockIdx.x, by = blockIdx.y;
    const int m0 = by * TM, n0 = bx * TN;

    const int lrow = tid >> 1;
    const int lseg = (tid & 1) * 4;
    const int sw = lrow & 7;
    const __nv_bfloat16* gA = g_A2 + (size_t)(m0 + lrow) * KBIG + lseg * 8;
    const __nv_bfloat16* gB = g_B2 + (size_t)(n0 + lrow) * KBIG + lseg * 8;
    const uint32_t sRowOff = lrow * 128;

#define LOAD_CHUNK(s, k) do {                                                   \
        uint32_t _a = sb + OFF_A(s) + sRowOff;                                  \
        uint32_t _b = sb + OFF_B(s) + sRowOff;                                  \
        _Pragma("unroll")                                                       \
        for (int j = 0; j < 4; j++) {                                           \
            cp16(_a + (((lseg + j) ^ sw) << 4), gA + (size_t)(k) * KCH + j * 8);\
            cp16(_b + (((lseg + j) ^ sw) << 4), gB + (size_t)(k) * KCH + j * 8);\
        }                                                                       \
        cp_commit();                                                            \
    } while (0)

    float acc[4][4][4];
#pragma unroll
    for (int mt = 0; mt < 4; mt++)
#pragma unroll
        for (int nt = 0; nt < 4; nt++)
#pragma unroll
            for (int i = 0; i < 4; i++) acc[mt][nt][i] = 0.0f;

    const int q = lane >> 3, rr = lane & 7;
    const int aRowBase = wr * 64 + rr + ((q & 1) << 3);
    const int bRowBase = wc * 32 + rr + ((q & 1) << 3);
    const int kgHalf = q >> 1;

    // precomputed per-ldm row offsets (constant across chunks)
    uint32_t aOff[4], bOff[2];
#pragma unroll
    for (int mt = 0; mt < 4; mt++) {
        int r = aRowBase + mt * 16;
        aOff[mt] = r * 128;
    }
#pragma unroll
    for (int np = 0; np < 2; np++) {
        int r = bRowBase + np * 16;
        bOff[np] = r * 128;
    }

    LOAD_CHUNK(0, 0);
    LOAD_CHUNK(1, 1);

#pragma unroll 3
    for (int k = 0; k < NCHUNK; k++) {
        if (k + 2 < NCHUNK) LOAD_CHUNK((k + 2) % STAGES, k + 2);
        if (k <= NCHUNK - 3)      cp_wait<2>();
        else if (k == NCHUNK - 2) cp_wait<1>();
        else                      cp_wait<0>();
        __syncthreads();

        const int s = k % STAGES;
        const uint32_t aBase = sb + OFF_A(s);
        const uint32_t bBase = sb + OFF_B(s);

        // double-buffered fragment pipeline over ks (mma order unchanged)
        uint32_t af[2][4][4], bf[2][2][4];
        {
            const int kg = kgHalf;  // ks = 0
#pragma unroll
            for (int np = 0; np < 2; np++) {
                int r = bRowBase + np * 16;
                ldm_x4(bf[0][np], bBase + bOff[np] + ((kg ^ (r & 7)) << 4));
            }
#pragma unroll
            for (int mt = 0; mt < 4; mt++) {
                int r = aRowBase + mt * 16;
                ldm_x4(af[0][mt], aBase + aOff[mt] + ((kg ^ (r & 7)) << 4));
            }
        }
#pragma unroll
        for (int ks = 0; ks < 4; ks++) {
            const int cur = ks & 1, nxt = cur ^ 1;
            if (ks < 3) {
                const int kg2 = (ks + 1) * 2 + kgHalf;
#pragma unroll
                for (int np = 0; np < 2; np++) {
                    int r = bRowBase + np * 16;
                    ldm_x4(bf[nxt][np], bBase + bOff[np] + ((kg2 ^ (r & 7)) << 4));
                }
#pragma unroll
                for (int mt = 0; mt < 4; mt++) {
                    int r = aRowBase + mt * 16;
                    ldm_x4(af[nxt][mt], aBase + aOff[mt] + ((kg2 ^ (r & 7)) << 4));
                }
            }
#pragma unroll
            for (int mt = 0; mt < 4; mt++)
#pragma unroll
                for (int nt = 0; nt < 4; nt++)
                    mma_bf16(acc[mt][nt], af[cur][mt],
                             bf[cur][nt >> 1][nt & 1], bf[cur][nt >> 1][(nt & 1) + 2]);
        }
        __syncthreads();
    }

    // ---------------- epilogue ----------------
    float rs[4][2];
    float cs[4][2];
#pragma unroll
    for (int mt = 0; mt < 4; mt++) { rs[mt][0] = 0.0f; rs[mt][1] = 0.0f; }
#pragma unroll
    for (int nt = 0; nt < 4; nt++) { cs[nt][0] = 0.0f; cs[nt][1] = 0.0f; }
    float tmax = 0.0f;

    const int rbase = m0 + wr * 64 + (lane >> 2);
    const int cbase = n0 + wc * 32 + (lane & 3) * 2;
#pragma unroll
    for (int mt = 0; mt < 4; mt++) {
#pragma unroll
        for (int p = 0; p < 2; p++) {
            const int grow = rbase + mt * 16 + p * 8;
            float* srow = g_S + (size_t)grow * NDIM + cbase;
#pragma unroll
            for (int nt = 0; nt < 4; nt++) {
                float e0 = __expf(fmaf(2.0f, acc[mt][nt][2 * p + 0], -2.0f));
                float e1 = __expf(fmaf(2.0f, acc[mt][nt][2 * p + 1], -2.0f));
                rs[mt][p] += e0 + e1;
                cs[nt][0] += e0;
                cs[nt][1] += e1;
                tmax = fmaxf(tmax, fmaxf(e0, e1));
                *(float2*)(srow + nt * 8) = make_float2(e0, e1);
            }
        }
    }

#pragma unroll
    for (int mt = 0; mt < 4; mt++) {
#pragma unroll
        for (int p = 0; p < 2; p++) {
            float v = rs[mt][p];
            v += __shfl_xor_sync(0xFFFFFFFFu, v, 1);
            v += __shfl_xor_sync(0xFFFFFFFFu, v, 2);
            if ((lane & 3) == 0) {
                int lr = wr * 64 + mt * 16 + (lane >> 2) + p * 8;
                redR[lr][wc] = v;
            }
        }
    }
#pragma unroll
    for (int nt = 0; nt < 4; nt++) {
#pragma unroll
        for (int j = 0; j < 2; j++) {
            float v = cs[nt][j];
            v += __shfl_xor_sync(0xFFFFFFFFu, v, 4);
            v += __shfl_xor_sync(0xFFFFFFFFu, v, 8);
            v += __shfl_xor_sync(0xFFFFFFFFu, v, 16);
            if (lane < 4) {
                int lc = wc * 32 + nt * 8 + lane * 2 + j;
                redC[wr][lc] = v;
            }
        }
    }
#pragma unroll
    for (int d = 16; d >= 1; d >>= 1)
        tmax = fmaxf(tmax, __shfl_xor_sync(0xFFFFFFFFu, tmax, d));
    if (lane == 0) smax[wid] = tmax;
    __syncthreads();
    if (tid == 0) {
        float s = smax[0];
#pragma unroll
        for (int i = 1; i < 8; i++) s = fmaxf(s, smax[i]);
        g_tileMaxS[by * 64 + bx] = s;
    }
    if (tid < 128) {
        float s = ((redR[tid][0] + redR[tid][1]) + redR[tid][2]) + redR[tid][3];
        g_Rpart[(size_t)(m0 + tid) * 64 + bx] = s;
        g_Cpart[(size_t)by * NDIM + (n0 + tid)] = redC[0][tid] + redC[1][tid];
    }
#undef LOAD_CHUNK
}

// ---------------- deterministic reduction of row/col sums -> reciprocals ----------------
__global__ void spm_reduce_rc_kernel() {
    int t = blockIdx.x * blockDim.x + threadIdx.x;
    if (t < MDIM) {
        float s = 0.0f;
        const float* p = g_Rpart + (size_t)t * 64;
#pragma unroll 8
        for (int i = 0; i < 64; i++) s += p[i];
        g_invR[t] = 1.0f / s;
    } else if (t < MDIM + NDIM) {
        int n = t - MDIM;
        float s = 0.0f;
        for (int i = 0; i < 64; i++) s += g_Cpart[(size_t)i * NDIM + n];
        g_invC[n] = 1.0f / s;
    }
}

// ---------------- tile bounds + threshold (single block, 1024 threads) ----------------
__global__ void spm_thr_kernel() {
    __shared__ float rgMin[64], rgMax[64], cgMin[64], cgMax[64];
    __shared__ unsigned int hist[8192];
    __shared__ unsigned int gsum[256];
    const int tid = threadIdx.x;

    for (int i = tid; i < 8192; i += 1024) hist[i] = 0u;
    if (tid < 64) {
        float mn = 3.4e38f, mx = 0.0f;
        const float* p = g_invR + tid * 128;
        for (int i = 0; i < 128; i++) { float v = p[i]; mn = fminf(mn, v); mx = fmaxf(mx, v); }
        rgMin[tid] = mn; rgMax[tid] = mx;
    } else if (tid < 128) {
        int g = tid - 64;
        float mn = 3.4e38f, mx = 0.0f;
        const float* p = g_invC + g * 128;
        for (int i = 0; i < 128; i++) { float v = p[i]; mn = fminf(mn, v); mx = fmaxf(mx, v); }
        cgMin[g] = mn; cgMax[g] = mx;
    }
    __syncthreads();

    for (int t = tid; t < NTILES; t += 1024) {
        int ty = t >> 6, tx = t & 63;
        float s = g_tileMaxS[t];
        float s2 = s * s;
        float L = s2 * rgMin[ty] * cgMin[tx];
        float U = s2 * rgMax[ty] * cgMax[tx] * 1.00001f;
        g_tileU[t] = U;
        atomicAdd(&hist[min(__float_as_uint(L) >> 18, 8191u)], 1u);
    }
    __syncthreads();

    if (tid < 256) {
        unsigned int s = 0;
        for (int i = 0; i < 32; i++) s += hist[tid * 32 + i];
        gsum[tid] = s;
    }
    __syncthreads();
    if (tid == 0) {
        unsigned int cum = 0;
        int g = 255;
        for (; g >= 0; g--) {
            if (cum + gsum[g] >= KSEL) break;
            cum += gsum[g];
        }
        if (g < 0) g = 0;
        int b = g * 32 + 31;
        for (; b > g * 32; b--) {
            cum += hist[b];
            if (cum >= KSEL) break;
        }
        g_thresh = ((unsigned int)b) << 18;
    }
}

// ---------------- gather candidates from tiles whose upper bound passes ----------------
__global__ void spm_select_kernel() {
    const int t = blockIdx.x;
    const float thrF = __uint_as_float(g_thresh);
    if (g_tileU[t] < thrF) return;
    const int ty = t >> 6, tx = t & 63;
    const int tid = threadIdx.x;

#pragma unroll 4
    for (int it = 0; it < 16; it++) {
        int f = it * 256 + tid;
        int r = f >> 5;
        int c4 = f & 31;
        int R = ty * 128 + r;
        int C = tx * 128 + c4 * 4;
        float4 s = *(const float4*)(g_S + (size_t)R * NDIM + C);
        float fr = g_invR[R];
        float4 ic = *(const float4*)(g_invC + C);
        float v[4];
        v[0] = s.x * s.x * fr * ic.x;
        v[1] = s.y * s.y * fr * ic.y;
        v[2] = s.z * s.z * fr * ic.z;
        v[3] = s.w * s.w * fr * ic.w;
        size_t i0 = (size_t)R * NDIM + C;
#pragma unroll
        for (int u = 0; u < 4; u++) {
            if (v[u] >= thrF) {
                int p = atomicAdd(&g_candCount, 1);
                if (p < CAND_CAP) {
                    g_candVal[p] = v[u];
                    g_candIdx[p] = (int)(i0 + u);
                }
            }
        }
    }
}

// ---------------- exact rank-based top-256 (matches lax.top_k tie-break) ----------------
__global__ void spm_topk_kernel(float* __restrict__ out) {
    int K = g_candCount;
    if (K > CAND_CAP) K = CAND_CAP;
    for (int c = blockIdx.x * blockDim.x + threadIdx.x; c < K;
         c += gridDim.x * blockDim.x) {
        const float vc = g_candVal[c];
        const int ic = g_candIdx[c];
        int rank = 0;
        for (int j = 0; j < K; j++) {
            const float vj = g_candVal[j];
            const int ij = g_candIdx[j];
            rank += (vj > vc) || (vj == vc && ij < ic);
        }
        if (rank < KSEL) {
            out[rank]            = (float)(ic >> 13);   // ref index = i // 8192
            out[KSEL + rank]     = (float)(ic & 8191);  // src index = i % 8192
            out[2 * KSEL + rank] = vc;                  // score
        }
    }
}

// ---------------- launch ----------------
extern "C" void kernel_launch(void* const* d_in, const int* in_sizes, int n_in,
                              void* d_out, int out_size) {
    const float* ref = (const float*)d_in[0];  // [8192, 256]
    const float* src = (const float*)d_in[1];  // [8192, 256]
    float* out = (float*)d_out;                // [768]: ref_idx | src_idx | scores

    cudaFuncSetAttribute(spm_gemm_mma_kernel,
                         cudaFuncAttributeMaxDynamicSharedMemorySize, SMEM_BYTES);

    spm_init_kernel<<<1, 32>>>();                             // launch #1
    spm_split_kernel<<<4096, 256>>>(ref, src);                // launch #2
    spm_nop_kernel<<<1, 32>>>();                              // launch #3 (pad: ncu captures #4)
    spm_gemm_mma_kernel<<<dim3(64, 64), 256, SMEM_BYTES>>>(); // launch #4  <- profiled
    spm_reduce_rc_kernel<<<64, 256>>>();
    spm_thr_kernel<<<1, 1024>>>();
    spm_select_kernel<<<NTILES, 256>>>();
    spm_topk_kernel<<<64, 256>>>(out);
}